// round 16
// baseline (speedup 1.0000x reference)
#include <cuda_runtime.h>
#include <math.h>
#include <stdint.h>

#define NBATCH 256
#define LEN    200
#define DM     256
#define NH     4
#define DK     64
#define NIS    288
#define NTI    10   // item weight types
#define NTQ    9    // intent weight types

#define NTOK_I (NBATCH * LEN)   // 51200
#define NTOK_Q (NBATCH * NIS)   // 73728
#define CAPI   8192             // per-type capacity
#define CAPQ   12288            // per-type capacity
#define MT     64               // M rows per block tile
#define XPAD   260              // smem row stride (conflict-free fragment LDS)

// ---------------- scratch (static device globals; no allocation) ------------
__device__ float g_Kbs[(size_t)NBATCH * NH * LEN * DK];
__device__ float g_Vbs[(size_t)NBATCH * NH * LEN * DK];
__device__ float g_Kba[(size_t)NBATCH * NH * LEN * DK];
__device__ float g_Vba[(size_t)NBATCH * NH * LEN * DK];
__device__ float g_Q  [(size_t)NBATCH * NH * NIS * DK];

__device__ int   g_cntI[NTI];
__device__ int   g_cntQ[NTQ];
__device__ int   g_listI[NTI * CAPI];
__device__ int   g_listQ[NTQ * CAPQ];
// fragment-swizzled weights: [t][nsub][ksub][lane] -> {b0_hi,b1_hi,b0_lo,b1_lo}
__device__ uint4 g_WfI[NTI * 64 * 32 * 32];   // item: N=512 -> 64 nsub
__device__ uint4 g_WfQ[NTQ * 32 * 32 * 32];   // intent: N=256 -> 32 nsub

// ---------------- helpers ---------------------------------------------------
__device__ __forceinline__ unsigned f2tf(float x) {
    unsigned r;
    asm("cvt.rna.tf32.f32 %0, %1;" : "=r"(r) : "f"(x));
    return r;
}

__device__ __forceinline__ void mma8(float* d,
                                     unsigned a0, unsigned a1, unsigned a2, unsigned a3,
                                     unsigned b0, unsigned b1) {
    asm("mma.sync.aligned.m16n8k8.row.col.f32.tf32.tf32.f32 "
        "{%0,%1,%2,%3},{%4,%5,%6,%7},{%8,%9},{%0,%1,%2,%3};"
        : "+f"(d[0]), "+f"(d[1]), "+f"(d[2]), "+f"(d[3])
        : "r"(a0), "r"(a1), "r"(a2), "r"(a3), "r"(b0), "r"(b1));
}

__device__ __forceinline__ float get_cn(float xf) {
    const float quarter = 24.0f / 4.0f;            // 6
    float safe = fmaxf(xf, quarter);
    float f1 = quarter + floorf(logf(4.0f * safe / 24.0f) /
                                logf(4.0f * 200.0f / 24.0f) * quarter);
    float upper = 24.0f / 2.0f - 1.0f;             // 11
    return (xf < quarter) ? xf : fminf(f1, upper);
}

// ---------------- setup kernels ---------------------------------------------
__global__ void zero_cnt_kernel() {
    int t = threadIdx.x;
    if (t < NTI) g_cntI[t] = 0;
    if (t < NTQ) g_cntQ[t] = 0;
}

__global__ void build_lists_kernel(const int* __restrict__ b_seq,
                                   const int* __restrict__ b_seq2) {
    int i = blockIdx.x * 256 + threadIdx.x;
    if (i < NTOK_I) {
        int t = b_seq[i];
        if (t >= 0 && t < NTI) {
            int p = atomicAdd(&g_cntI[t], 1);
            if (p < CAPI) g_listI[t * CAPI + p] = i;
        }
    }
    if (i < NTOK_Q) {
        int t = b_seq2[i];
        if (t >= 0 && t < NTQ) {
            int p = atomicAdd(&g_cntQ[t], 1);
            if (p < CAPQ) g_listQ[t * CAPQ + p] = i;
        }
    }
}

// item weights -> swizzled hi/lo fragments. idx = ((t*64+ns)*32+ks)*32+lane
__global__ void wfrag_item_kernel(const float* __restrict__ W) {
    int idx = blockIdx.x * 256 + threadIdx.x;
    if (idx >= NTI * 64 * 32 * 32) return;
    int lane = idx & 31, ks = (idx >> 5) & 31, ns = (idx >> 10) & 63, t = idx >> 16;
    int n = ns * 8 + (lane >> 2);
    int k = ks * 8 + (lane & 3);
    int m = (n < 256) ? 0 : 1;
    int c = n & 255;
    const float* Wm = W + ((size_t)(m * NTI + t)) * DM * DM;
    float w0 = Wm[k * DM + c];
    float w1 = Wm[(k + 4) * DM + c];
    unsigned h0 = f2tf(w0), h1 = f2tf(w1);
    unsigned l0 = f2tf(w0 - __uint_as_float(h0));
    unsigned l1 = f2tf(w1 - __uint_as_float(h1));
    g_WfI[idx] = make_uint4(h0, h1, l0, l1);
}

// intent weights. idx = ((t*32+ns)*32+ks)*32+lane
__global__ void wfrag_q_kernel(const float* __restrict__ W) {
    int idx = blockIdx.x * 256 + threadIdx.x;
    if (idx >= NTQ * 32 * 32 * 32) return;
    int lane = idx & 31, ks = (idx >> 5) & 31, ns = (idx >> 10) & 31, t = idx >> 15;
    int n = ns * 8 + (lane >> 2);
    int k = ks * 8 + (lane & 3);
    const float* Wm = W + (size_t)t * DM * DM;
    float w0 = Wm[k * DM + n];
    float w1 = Wm[(k + 4) * DM + n];
    unsigned h0 = f2tf(w0), h1 = f2tf(w1);
    unsigned l0 = f2tf(w0 - __uint_as_float(h0));
    unsigned l1 = f2tf(w1 - __uint_as_float(h1));
    g_WfQ[idx] = make_uint4(h0, h1, l0, l1);
}

// ---------------------------------------------------------------------------
// Item projection GEMM: C[64 x 512] = X[64 x 256] * Wcat[256 x 512].
// Retiled: 8 warps = 2(m-pairs) x 4(n-slices); pass0 = K cols (4xTF32,
// bit-identical), pass1 = V cols (3xTF32: al*bl dropped — V error ~2^-22
// relative, cannot affect top-k). acc0/acc1 MMA streams interleaved to break
// RAW chains; per-accumulator order unchanged.
// ---------------------------------------------------------------------------
__global__ __launch_bounds__(256, 2)
void proj_item_mma(const float* __restrict__ item, int useList)
{
    int t, count;
    const int* list;
    float* outK;
    float* outV;
    if (useList) {
        t = blockIdx.y;
        count = min(g_cntI[t], CAPI);
        list = g_listI + t * CAPI;
        outK = g_Kbs; outV = g_Vbs;
    } else {
        t = NTI - 1;
        count = NTOK_I;
        list = nullptr;
        outK = g_Kba; outV = g_Vba;
    }
    int row0 = blockIdx.x * MT;
    if (row0 >= count) return;

    extern __shared__ float xs[];              // [MT][XPAD]
    __shared__ int stok[MT];
    int tid = threadIdx.x;

    if (tid < MT) {
        int gr = row0 + tid;
        stok[tid] = (gr < count) ? (list ? list[gr] : gr) : -1;
    }
    __syncthreads();

    // load A tile (64 x 256)
    {
        int r = tid >> 2, q4 = tid & 3;
        int tok = stok[r];
        const float* src = item + (size_t)max(tok, 0) * DM;
#pragma unroll
        for (int i = 0; i < 16; ++i) {
            int qd = q4 + i * 4;
            float4 v = make_float4(0.f, 0.f, 0.f, 0.f);
            if (tok >= 0) v = reinterpret_cast<const float4*>(src)[qd];
            *reinterpret_cast<float4*>(&xs[r * XPAD + qd * 4]) = v;
        }
    }
    __syncthreads();

    int wid = tid >> 5, lane = tid & 31;
    int wm = wid >> 2, wn = wid & 3;       // wm: 2 m-pairs; wn: 4 n-slices
    int la = lane >> 2, lb = lane & 3;
    int mbase = wm * 32 + la;
    const float* x0 = &xs[(mbase     ) * XPAD];
    const float* x1 = &xs[(mbase +  8) * XPAD];
    const float* x2 = &xs[(mbase + 16) * XPAD];
    const float* x3 = &xs[(mbase + 24) * XPAD];

    int gr0 = row0 + mbase;
    int tok0 = (gr0      < count) ? (list ? list[gr0]      : gr0)      : -1;
    int tok1 = (gr0 + 8  < count) ? (list ? list[gr0 + 8]  : gr0 + 8)  : -1;
    int tok2 = (gr0 + 16 < count) ? (list ? list[gr0 + 16] : gr0 + 16) : -1;
    int tok3 = (gr0 + 24 < count) ? (list ? list[gr0 + 24] : gr0 + 24) : -1;
    int b0_ = (tok0 >= 0) ? tok0 / LEN : 0, n0_ = (tok0 >= 0) ? tok0 % LEN : 0;
    int b1_ = (tok1 >= 0) ? tok1 / LEN : 0, n1_ = (tok1 >= 0) ? tok1 % LEN : 0;
    int b2_ = (tok2 >= 0) ? tok2 / LEN : 0, n2_ = (tok2 >= 0) ? tok2 % LEN : 0;
    int b3_ = (tok3 >= 0) ? tok3 / LEN : 0, n3_ = (tok3 >= 0) ? tok3 % LEN : 0;

    for (int pass = 0; pass < 2; ++pass) {
        int nsb = (pass * 4 + wn) * 8;     // nsub base (8 per warp)
        const uint4* wf = g_WfI + (((size_t)t * 64 + nsb) * 32) * 32 + lane;

        float acc0[8][4], acc1[8][4];
#pragma unroll
        for (int ns = 0; ns < 8; ++ns)
#pragma unroll
            for (int j = 0; j < 4; ++j) { acc0[ns][j] = 0.0f; acc1[ns][j] = 0.0f; }

        for (int ks = 0; ks < 32; ++ks) {
            int k0 = ks * 8;
            float f0 = x0[k0 + lb],     f1 = x1[k0 + lb];
            float f2 = x0[k0 + lb + 4], f3 = x1[k0 + lb + 4];
            unsigned ah0 = f2tf(f0), ah1 = f2tf(f1), ah2 = f2tf(f2), ah3 = f2tf(f3);
            unsigned al0 = f2tf(f0 - __uint_as_float(ah0));
            unsigned al1 = f2tf(f1 - __uint_as_float(ah1));
            unsigned al2 = f2tf(f2 - __uint_as_float(ah2));
            unsigned al3 = f2tf(f3 - __uint_as_float(ah3));
            float g0 = x2[k0 + lb],     g1 = x3[k0 + lb];
            float g2 = x2[k0 + lb + 4], g3 = x3[k0 + lb + 4];
            unsigned ch0 = f2tf(g0), ch1 = f2tf(g1), ch2 = f2tf(g2), ch3 = f2tf(g3);
            unsigned cl0 = f2tf(g0 - __uint_as_float(ch0));
            unsigned cl1 = f2tf(g1 - __uint_as_float(ch1));
            unsigned cl2 = f2tf(g2 - __uint_as_float(ch2));
            unsigned cl3 = f2tf(g3 - __uint_as_float(ch3));
            const uint4* wfk = wf + ks * 32;
#pragma unroll
            for (int ns = 0; ns < 8; ++ns) {
                uint4 w = wfk[(size_t)ns * 1024];
                if (pass == 0) {                                  // K: full 4x
                    mma8(acc0[ns], al0, al1, al2, al3, w.z, w.w); // al*bl
                    mma8(acc1[ns], cl0, cl1, cl2, cl3, w.z, w.w);
                }
                mma8(acc0[ns], ah0, ah1, ah2, ah3, w.z, w.w);     // ah*bl
                mma8(acc1[ns], ch0, ch1, ch2, ch3, w.z, w.w);
                mma8(acc0[ns], al0, al1, al2, al3, w.x, w.y);     // al*bh
                mma8(acc1[ns], cl0, cl1, cl2, cl3, w.x, w.y);
                mma8(acc0[ns], ah0, ah1, ah2, ah3, w.x, w.y);     // ah*bh
                mma8(acc1[ns], ch0, ch1, ch2, ch3, w.x, w.y);
            }
        }

#pragma unroll
        for (int ns = 0; ns < 8; ++ns) {
            int cg = (nsb + ns) * 8 + lb * 2;
            int mat = cg >> 8, hh = (cg >> 6) & 3, kd = cg & 63;
            float* base = mat ? outV : outK;
            if (tok0 >= 0)
                *reinterpret_cast<float2*>(&base[(((size_t)b0_ * NH + hh) * LEN + n0_) * DK + kd]) =
                    make_float2(acc0[ns][0], acc0[ns][1]);
            if (tok1 >= 0)
                *reinterpret_cast<float2*>(&base[(((size_t)b1_ * NH + hh) * LEN + n1_) * DK + kd]) =
                    make_float2(acc0[ns][2], acc0[ns][3]);
            if (tok2 >= 0)
                *reinterpret_cast<float2*>(&base[(((size_t)b2_ * NH + hh) * LEN + n2_) * DK + kd]) =
                    make_float2(acc1[ns][0], acc1[ns][1]);
            if (tok3 >= 0)
                *reinterpret_cast<float2*>(&base[(((size_t)b3_ * NH + hh) * LEN + n3_) * DK + kd]) =
                    make_float2(acc1[ns][2], acc1[ns][3]);
        }
        __syncthreads();
    }
}

// ---------------------------------------------------------------------------
// Intent projection GEMM: C[64 x 256] = X[64 x 256] * W[256 x 256], 4xTF32
// (Q feeds scores/top-k: keep exact). Interleaved acc0/acc1 streams.
// ---------------------------------------------------------------------------
__global__ __launch_bounds__(256, 2)
void proj_q_mma(const float* __restrict__ intent)
{
    int t = blockIdx.y;
    int count = min(g_cntQ[t], CAPQ);
    const int* list = g_listQ + t * CAPQ;
    int row0 = blockIdx.x * MT;
    if (row0 >= count) return;

    extern __shared__ float xs[];              // [MT][XPAD]
    __shared__ int stok[MT];
    int tid = threadIdx.x;

    if (tid < MT) {
        int gr = row0 + tid;
        stok[tid] = (gr < count) ? list[gr] : -1;
    }
    __syncthreads();

    {
        int r = tid >> 2, q4 = tid & 3;
        int tok = stok[r];
        const float* src = intent + (size_t)((tok >= 0 ? tok : 0) % NIS) * DM;
#pragma unroll
        for (int i = 0; i < 16; ++i) {
            int qd = q4 + i * 4;
            float4 v = make_float4(0.f, 0.f, 0.f, 0.f);
            if (tok >= 0) v = reinterpret_cast<const float4*>(src)[qd];
            *reinterpret_cast<float4*>(&xs[r * XPAD + qd * 4]) = v;
        }
    }
    __syncthreads();

    int wid = tid >> 5, lane = tid & 31;
    int wm = wid >> 2, wn = wid & 3;
    int la = lane >> 2, lb = lane & 3;
    int mbase = wm * 32 + la;
    const float* x0 = &xs[(mbase     ) * XPAD];
    const float* x1 = &xs[(mbase +  8) * XPAD];
    const float* x2 = &xs[(mbase + 16) * XPAD];
    const float* x3 = &xs[(mbase + 24) * XPAD];

    int gr0 = row0 + mbase;
    int tok0 = (gr0      < count) ? list[gr0]      : -1;
    int tok1 = (gr0 + 8  < count) ? list[gr0 + 8]  : -1;
    int tok2 = (gr0 + 16 < count) ? list[gr0 + 16] : -1;
    int tok3 = (gr0 + 24 < count) ? list[gr0 + 24] : -1;
    int b0_ = (tok0 >= 0) ? tok0 / NIS : 0, q0_ = (tok0 >= 0) ? tok0 % NIS : 0;
    int b1_ = (tok1 >= 0) ? tok1 / NIS : 0, q1_ = (tok1 >= 0) ? tok1 % NIS : 0;
    int b2_ = (tok2 >= 0) ? tok2 / NIS : 0, q2_ = (tok2 >= 0) ? tok2 % NIS : 0;
    int b3_ = (tok3 >= 0) ? tok3 / NIS : 0, q3_ = (tok3 >= 0) ? tok3 % NIS : 0;

    int nsb = wn * 8;
    const uint4* wf = g_WfQ + (((size_t)t * 32 + nsb) * 32) * 32 + lane;

    float acc0[8][4], acc1[8][4];
#pragma unroll
    for (int ns = 0; ns < 8; ++ns)
#pragma unroll
        for (int j = 0; j < 4; ++j) { acc0[ns][j] = 0.0f; acc1[ns][j] = 0.0f; }

    for (int ks = 0; ks < 32; ++ks) {
        int k0 = ks * 8;
        float f0 = x0[k0 + lb],     f1 = x1[k0 + lb];
        float f2 = x0[k0 + lb + 4], f3 = x1[k0 + lb + 4];
        unsigned ah0 = f2tf(f0), ah1 = f2tf(f1), ah2 = f2tf(f2), ah3 = f2tf(f3);
        unsigned al0 = f2tf(f0 - __uint_as_float(ah0));
        unsigned al1 = f2tf(f1 - __uint_as_float(ah1));
        unsigned al2 = f2tf(f2 - __uint_as_float(ah2));
        unsigned al3 = f2tf(f3 - __uint_as_float(ah3));
        float g0 = x2[k0 + lb],     g1 = x3[k0 + lb];
        float g2 = x2[k0 + lb + 4], g3 = x3[k0 + lb + 4];
        unsigned ch0 = f2tf(g0), ch1 = f2tf(g1), ch2 = f2tf(g2), ch3 = f2tf(g3);
        unsigned cl0 = f2tf(g0 - __uint_as_float(ch0));
        unsigned cl1 = f2tf(g1 - __uint_as_float(ch1));
        unsigned cl2 = f2tf(g2 - __uint_as_float(ch2));
        unsigned cl3 = f2tf(g3 - __uint_as_float(ch3));
        const uint4* wfk = wf + ks * 32;
#pragma unroll
        for (int ns = 0; ns < 8; ++ns) {
            uint4 w = wfk[(size_t)ns * 1024];
            mma8(acc0[ns], al0, al1, al2, al3, w.z, w.w);
            mma8(acc1[ns], cl0, cl1, cl2, cl3, w.z, w.w);
            mma8(acc0[ns], ah0, ah1, ah2, ah3, w.z, w.w);
            mma8(acc1[ns], ch0, ch1, ch2, ch3, w.z, w.w);
            mma8(acc0[ns], al0, al1, al2, al3, w.x, w.y);
            mma8(acc1[ns], cl0, cl1, cl2, cl3, w.x, w.y);
            mma8(acc0[ns], ah0, ah1, ah2, ah3, w.x, w.y);
            mma8(acc1[ns], ch0, ch1, ch2, ch3, w.x, w.y);
        }
    }

#pragma unroll
    for (int ns = 0; ns < 8; ++ns) {
        int cg = (nsb + ns) * 8 + lb * 2;
        int hh = cg >> 6, kd = cg & 63;
        if (tok0 >= 0)
            *reinterpret_cast<float2*>(&g_Q[(((size_t)b0_ * NH + hh) * NIS + q0_) * DK + kd]) =
                make_float2(acc0[ns][0], acc0[ns][1]);
        if (tok1 >= 0)
            *reinterpret_cast<float2*>(&g_Q[(((size_t)b1_ * NH + hh) * NIS + q1_) * DK + kd]) =
                make_float2(acc0[ns][2], acc0[ns][3]);
        if (tok2 >= 0)
            *reinterpret_cast<float2*>(&g_Q[(((size_t)b2_ * NH + hh) * NIS + q2_) * DK + kd]) =
                make_float2(acc1[ns][0], acc1[ns][1]);
        if (tok3 >= 0)
            *reinterpret_cast<float2*>(&g_Q[(((size_t)b3_ * NH + hh) * NIS + q3_) * DK + kd]) =
                make_float2(acc1[ns][2], acc1[ns][3]);
    }
}

// ---------------------------------------------------------------------------
// Attention (R7-exact): scores + softmax + top-k + sparse p@V, int-mask loads.
// ---------------------------------------------------------------------------
__device__ __forceinline__ void mask_scale(float (&p)[25], const int* __restrict__ mrow)
{
#pragma unroll
    for (int i = 0; i < 25; ++i) {
        float s = p[i] * 0.125f;
        if (mrow[i] == 0) s = -1e30f;
        p[i] = s;
    }
}

__device__ __forceinline__ void softmax_topk(float (&p)[25], int g, int nb, int kk,
                                             int qg, float* keptP, int* keptI)
{
    float mx = -3.4e38f;
#pragma unroll
    for (int i = 0; i < 25; ++i) mx = fmaxf(mx, p[i]);
#pragma unroll
    for (int off = 1; off < 8; off <<= 1)
        mx = fmaxf(mx, __shfl_xor_sync(0xffffffffu, mx, off));
    float sum = 0.0f;
#pragma unroll
    for (int i = 0; i < 25; ++i) { float e = expf(p[i] - mx); p[i] = e; sum += e; }
#pragma unroll
    for (int off = 1; off < 8; off <<= 1)
        sum += __shfl_xor_sync(0xffffffffu, sum, off);
    float inv = 1.0f / sum;
#pragma unroll
    for (int i = 0; i < 25; ++i) p[i] *= inv;

    for (int it = 0; it < kk; ++it) {
        float bv = -2.0f; int bi = 0x40000000;
#pragma unroll
        for (int i = 0; i < 25; ++i) {
            if (p[i] > bv) { bv = p[i]; bi = nb + i; }
        }
#pragma unroll
        for (int off = 1; off < 8; off <<= 1) {
            float ov = __shfl_xor_sync(0xffffffffu, bv, off);
            int   oi = __shfl_xor_sync(0xffffffffu, bi, off);
            if (ov > bv || (ov == bv && oi < bi)) { bv = ov; bi = oi; }
        }
#pragma unroll
        for (int i = 0; i < 25; ++i)
            if (nb + i == bi) p[i] = -1.0f;
        if (g == 0) { keptP[qg * 12 + it] = bv; keptI[qg * 12 + it] = bi; }
    }
}

__global__ __launch_bounds__(256, 2)
void attn_kernel(const int* __restrict__ mask,
                 const int* __restrict__ type_cnt,
                 float* __restrict__ out)
{
    extern __shared__ float sm[];
    float* KV    = sm;
    float* Qs    = KV + 64 * LEN;
    float* keptP = Qs + 64 * 65;
    int*   keptI = (int*)(keptP + NIS * 12);
    __shared__ int skk[9];

    int bh = blockIdx.x;
    int b = bh >> 2, h = bh & 3;
    int tid = threadIdx.x;
    int g = tid & 7, qpair = tid >> 3;
    int nb = g * 25;

    if (tid < 9) {
        int v;
        if (tid < 8) v = type_cnt[b * 9 + 1 + tid];
        else { v = 0; for (int i = 0; i < 9; ++i) v += type_cnt[b * 9 + i]; }
        skk[tid] = (int)get_cn((float)v);
    }

    const size_t bhoff = ((size_t)(b * NH + h)) * LEN * DK;
    const size_t qoff  = ((size_t)(b * NH + h)) * NIS * DK;

    {
        const float* Ksrc = g_Kbs + bhoff;
        for (int idx = tid; idx < LEN * DK; idx += 256) {
            int n = idx >> 6, k = idx & 63;
            KV[k * LEN + n] = Ksrc[idx];
        }
    }
    __syncthreads();

    for (int pass = 0; pass < 4; ++pass) {
        int qb = pass * 64;
        for (int idx = tid; idx < 64 * DK; idx += 256) {
            int q = idx >> 6, k = idx & 63;
            Qs[q * 65 + k] = g_Q[qoff + (size_t)(qb + q) * DK + k];
        }
        __syncthreads();

        float p0[25], p1[25];
#pragma unroll
        for (int i = 0; i < 25; ++i) { p0[i] = 0.0f; p1[i] = 0.0f; }
        const float* qrow0 = &Qs[qpair * 65];
        const float* qrow1 = &Qs[(qpair + 32) * 65];
        for (int k = 0; k < DK; ++k) {
            float qv0 = qrow0[k], qv1 = qrow1[k];
            const float* kr = &KV[k * LEN + nb];
#pragma unroll
            for (int i = 0; i < 25; ++i) {
                float kv = kr[i];
                p0[i] = fmaf(qv0, kv, p0[i]);
                p1[i] = fmaf(qv1, kv, p1[i]);
            }
        }
        int q0 = qb + qpair, q1 = q0 + 32;
        mask_scale(p0, mask + ((size_t)b * NIS + q0) * LEN + nb);
        mask_scale(p1, mask + ((size_t)b * NIS + q1) * LEN + nb);
        softmax_topk(p0, g, nb, skk[q0 >> 5], q0, keptP, keptI);
        softmax_topk(p1, g, nb, skk[q1 >> 5], q1, keptP, keptI);
        __syncthreads();
    }

    // ---- Ba scores ----
    {
        const float* Ksrc = g_Kba + bhoff;
        for (int idx = tid; idx < LEN * DK; idx += 256) {
            int n = idx >> 6, k = idx & 63;
            KV[k * LEN + n] = Ksrc[idx];
        }
        for (int idx = tid; idx < 32 * DK; idx += 256) {
            int q = idx >> 6, k = idx & 63;
            Qs[q * 65 + k] = g_Q[qoff + (size_t)(256 + q) * DK + k];
        }
    }
    __syncthreads();
    {
        float p0[25];
#pragma unroll
        for (int i = 0; i < 25; ++i) p0[i] = 0.0f;
        const float* qrow0 = &Qs[qpair * 65];
        for (int k = 0; k < DK; ++k) {
            float qv0 = qrow0[k];
            const float* kr = &KV[k * LEN + nb];
#pragma unroll
            for (int i = 0; i < 25; ++i) p0[i] = fmaf(qv0, kr[i], p0[i]);
        }
        int q0 = 256 + qpair;
        mask_scale(p0, mask + ((size_t)b * NIS + q0) * LEN + nb);
        softmax_topk(p0, g, nb, skk[8], q0, keptP, keptI);
    }
    __syncthreads();

    // ---- Bs sparse output ----
    {
        const float* Vsrc = g_Vbs + bhoff;
        for (int idx = tid; idx < LEN * DK; idx += 256) KV[idx] = Vsrc[idx];
    }
    __syncthreads();
    int qloc = tid >> 3, d0 = (tid & 7) * 8;
    for (int pass = 0; pass < 8; ++pass) {
        int q = pass * 32 + qloc;
        int kk = skk[q >> 5];
        float4 o0 = {0, 0, 0, 0}, o1 = {0, 0, 0, 0};
        for (int j = 0; j < kk; ++j) {
            float pv = keptP[q * 12 + j];
            int   n  = keptI[q * 12 + j];
            const float4* vr = reinterpret_cast<const float4*>(&KV[n * DK + d0]);
            float4 v0 = vr[0], v1 = vr[1];
            o0.x = fmaf(pv, v0.x, o0.x); o0.y = fmaf(pv, v0.y, o0.y);
            o0.z = fmaf(pv, v0.z, o0.z); o0.w = fmaf(pv, v0.w, o0.w);
            o1.x = fmaf(pv, v1.x, o1.x); o1.y = fmaf(pv, v1.y, o1.y);
            o1.z = fmaf(pv, v1.z, o1.z); o1.w = fmaf(pv, v1.w, o1.w);
        }
        float* orow = out + ((size_t)b * NIS + q) * (NH * DK) + h * DK + d0;
        reinterpret_cast<float4*>(orow)[0] = o0;
        reinterpret_cast<float4*>(orow)[1] = o1;
    }
    __syncthreads();

    // ---- Ba sparse output ----
    {
        const float* Vsrc = g_Vba + bhoff;
        for (int idx = tid; idx < LEN * DK; idx += 256) KV[idx] = Vsrc[idx];
    }
    __syncthreads();
    {
        int q = 256 + qloc;
        int kk = skk[8];
        float4 o0 = {0, 0, 0, 0}, o1 = {0, 0, 0, 0};
        for (int j = 0; j < kk; ++j) {
            float pv = keptP[q * 12 + j];
            int   n  = keptI[q * 12 + j];
            const float4* vr = reinterpret_cast<const float4*>(&KV[n * DK + d0]);
            float4 v0 = vr[0], v1 = vr[1];
            o0.x = fmaf(pv, v0.x, o0.x); o0.y = fmaf(pv, v0.y, o0.y);
            o0.z = fmaf(pv, v0.z, o0.z); o0.w = fmaf(pv, v0.w, o0.w);
            o1.x = fmaf(pv, v1.x, o1.x); o1.y = fmaf(pv, v1.y, o1.y);
            o1.z = fmaf(pv, v1.z, o1.z); o1.w = fmaf(pv, v1.w, o1.w);
        }
        float* orow = out + ((size_t)b * NIS + q) * (NH * DK) + h * DK + d0;
        reinterpret_cast<float4*>(orow)[0] = o0;
        reinterpret_cast<float4*>(orow)[1] = o1;
    }
}

// ---------------------------------------------------------------------------
static const int ATTN_SMEM = (64 * LEN + 64 * 65 + NIS * 12) * 4 + NIS * 12 * 4;
static const int PROJ_SMEM = MT * XPAD * 4;   // 66560 B

extern "C" void kernel_launch(void* const* d_in, const int* in_sizes, int n_in,
                              void* d_out, int out_size)
{
    const float* item     = (const float*)d_in[0];
    const float* intent   = (const float*)d_in[1];
    const int*   mask     = (const int*)  d_in[2];
    const int*   b_seq    = (const int*)  d_in[3];
    const int*   b_seq2   = (const int*)  d_in[4];
    const int*   type_cnt = (const int*)  d_in[5];
    const float* W_item   = (const float*)d_in[6];
    const float* W_intent = (const float*)d_in[7];
    float* out = (float*)d_out;

    cudaFuncSetAttribute(attn_kernel,    cudaFuncAttributeMaxDynamicSharedMemorySize, ATTN_SMEM);
    cudaFuncSetAttribute(proj_item_mma,  cudaFuncAttributeMaxDynamicSharedMemorySize, PROJ_SMEM);
    cudaFuncSetAttribute(proj_q_mma,     cudaFuncAttributeMaxDynamicSharedMemorySize, PROJ_SMEM);

    // Launch order keeps proj_item_mma (Bs) in the profiler capture slot (#4).
    zero_cnt_kernel  <<<1, 32>>>();                                          // 1
    build_lists_kernel<<<(NTOK_Q + 255) / 256, 256>>>(b_seq, b_seq2);        // 2
    wfrag_item_kernel<<<(NTI * 64 * 32 * 32 + 255) / 256, 256>>>(W_item);    // 3
    proj_item_mma    <<<dim3(CAPI / MT, NTI), 256, PROJ_SMEM>>>(item, 1);    // 4 <- captured
    wfrag_q_kernel   <<<(NTQ * 32 * 32 * 32 + 255) / 256, 256>>>(W_intent);  // 5
    proj_item_mma    <<<dim3(NTOK_I / MT, 1), 256, PROJ_SMEM>>>(item, 0);    // 6
    proj_q_mma       <<<dim3(CAPQ / MT, NTQ), 256, PROJ_SMEM>>>(intent);     // 7
    attn_kernel      <<<NBATCH * NH, 256, ATTN_SMEM>>>(mask, type_cnt, out); // 8
}

// round 17
// speedup vs baseline: 1.0672x; 1.0672x over previous
#include <cuda_runtime.h>
#include <math.h>
#include <stdint.h>

#define NBATCH 256
#define LEN    200
#define DM     256
#define NH     4
#define DK     64
#define NIS    288
#define NTI    10   // item weight types
#define NTQ    9    // intent weight types

#define NTOK_I (NBATCH * LEN)   // 51200
#define NTOK_Q (NBATCH * NIS)   // 73728
#define CAPI   8192             // per-type capacity
#define CAPQ   12288            // per-type capacity
#define MT     64               // M rows per block tile
#define XPAD   260              // smem row stride (conflict-free fragment LDS)

// ---------------- scratch (static device globals; no allocation) ------------
__device__ float g_Kbs[(size_t)NBATCH * NH * LEN * DK];
__device__ float g_Vbs[(size_t)NBATCH * NH * LEN * DK];
__device__ float g_Kba[(size_t)NBATCH * NH * LEN * DK];
__device__ float g_Vba[(size_t)NBATCH * NH * LEN * DK];
__device__ float g_Q  [(size_t)NBATCH * NH * NIS * DK];

__device__ int   g_cntI[NTI];
__device__ int   g_cntQ[NTQ];
__device__ int   g_listI[NTI * CAPI];
__device__ int   g_listQ[NTQ * CAPQ];
// fragment-swizzled weights: [t][nsub][ksub][lane] -> {b0_hi,b1_hi,b0_lo,b1_lo}
__device__ uint4 g_WfI[NTI * 64 * 32 * 32];   // item: N=512 -> 64 nsub
__device__ uint4 g_WfQ[NTQ * 32 * 32 * 32];   // intent: N=256 -> 32 nsub

// ---------------- helpers ---------------------------------------------------
__device__ __forceinline__ unsigned f2tf(float x) {
    unsigned r;
    asm("cvt.rna.tf32.f32 %0, %1;" : "=r"(r) : "f"(x));
    return r;
}

__device__ __forceinline__ void mma8(float* d,
                                     unsigned a0, unsigned a1, unsigned a2, unsigned a3,
                                     unsigned b0, unsigned b1) {
    asm("mma.sync.aligned.m16n8k8.row.col.f32.tf32.tf32.f32 "
        "{%0,%1,%2,%3},{%4,%5,%6,%7},{%8,%9},{%0,%1,%2,%3};"
        : "+f"(d[0]), "+f"(d[1]), "+f"(d[2]), "+f"(d[3])
        : "r"(a0), "r"(a1), "r"(a2), "r"(a3), "r"(b0), "r"(b1));
}

__device__ __forceinline__ float get_cn(float xf) {
    const float quarter = 24.0f / 4.0f;            // 6
    float safe = fmaxf(xf, quarter);
    float f1 = quarter + floorf(logf(4.0f * safe / 24.0f) /
                                logf(4.0f * 200.0f / 24.0f) * quarter);
    float upper = 24.0f / 2.0f - 1.0f;             // 11
    return (xf < quarter) ? xf : fminf(f1, upper);
}

// ---------------- setup kernels ---------------------------------------------
__global__ void zero_cnt_kernel() {
    int t = threadIdx.x;
    if (t < NTI) g_cntI[t] = 0;
    if (t < NTQ) g_cntQ[t] = 0;
}

__global__ void build_lists_kernel(const int* __restrict__ b_seq,
                                   const int* __restrict__ b_seq2) {
    int i = blockIdx.x * 256 + threadIdx.x;
    if (i < NTOK_I) {
        int t = b_seq[i];
        if (t >= 0 && t < NTI) {
            int p = atomicAdd(&g_cntI[t], 1);
            if (p < CAPI) g_listI[t * CAPI + p] = i;
        }
    }
    if (i < NTOK_Q) {
        int t = b_seq2[i];
        if (t >= 0 && t < NTQ) {
            int p = atomicAdd(&g_cntQ[t], 1);
            if (p < CAPQ) g_listQ[t * CAPQ + p] = i;
        }
    }
}

// item weights -> swizzled hi/lo fragments. idx = ((t*64+ns)*32+ks)*32+lane
__global__ void wfrag_item_kernel(const float* __restrict__ W) {
    int idx = blockIdx.x * 256 + threadIdx.x;
    if (idx >= NTI * 64 * 32 * 32) return;
    int lane = idx & 31, ks = (idx >> 5) & 31, ns = (idx >> 10) & 63, t = idx >> 16;
    int n = ns * 8 + (lane >> 2);
    int k = ks * 8 + (lane & 3);
    int m = (n < 256) ? 0 : 1;
    int c = n & 255;
    const float* Wm = W + ((size_t)(m * NTI + t)) * DM * DM;
    float w0 = Wm[k * DM + c];
    float w1 = Wm[(k + 4) * DM + c];
    unsigned h0 = f2tf(w0), h1 = f2tf(w1);
    unsigned l0 = f2tf(w0 - __uint_as_float(h0));
    unsigned l1 = f2tf(w1 - __uint_as_float(h1));
    g_WfI[idx] = make_uint4(h0, h1, l0, l1);
}

// intent weights. idx = ((t*32+ns)*32+ks)*32+lane
__global__ void wfrag_q_kernel(const float* __restrict__ W) {
    int idx = blockIdx.x * 256 + threadIdx.x;
    if (idx >= NTQ * 32 * 32 * 32) return;
    int lane = idx & 31, ks = (idx >> 5) & 31, ns = (idx >> 10) & 31, t = idx >> 15;
    int n = ns * 8 + (lane >> 2);
    int k = ks * 8 + (lane & 3);
    const float* Wm = W + (size_t)t * DM * DM;
    float w0 = Wm[k * DM + n];
    float w1 = Wm[(k + 4) * DM + n];
    unsigned h0 = f2tf(w0), h1 = f2tf(w1);
    unsigned l0 = f2tf(w0 - __uint_as_float(h0));
    unsigned l1 = f2tf(w1 - __uint_as_float(h1));
    g_WfQ[idx] = make_uint4(h0, h1, l0, l1);
}

// ---------------------------------------------------------------------------
// Item projection GEMM: C[64 x 512] = X[64 x 256] * Wcat[256 x 512].
// R13 tiling: 8 warps = 2(m-pairs) x 4(n-slices). Pass 0 (K cols): full
// 4xTF32, instruction-for-instruction identical to the R13 winner. Pass 1
// (V cols): 3xTF32 (al*bl dropped; V error ~2^-22 relative, linear in output).
// Two straight-line blocks -> no branch in hot code.
// ---------------------------------------------------------------------------
__global__ __launch_bounds__(256, 2)
void proj_item_mma(const float* __restrict__ item, int useList)
{
    int t, count;
    const int* list;
    float* outK;
    float* outV;
    if (useList) {
        t = blockIdx.y;
        count = min(g_cntI[t], CAPI);
        list = g_listI + t * CAPI;
        outK = g_Kbs; outV = g_Vbs;
    } else {
        t = NTI - 1;
        count = NTOK_I;
        list = nullptr;
        outK = g_Kba; outV = g_Vba;
    }
    int row0 = blockIdx.x * MT;
    if (row0 >= count) return;

    extern __shared__ float xs[];              // [MT][XPAD]
    __shared__ int stok[MT];
    int tid = threadIdx.x;

    if (tid < MT) {
        int gr = row0 + tid;
        stok[tid] = (gr < count) ? (list ? list[gr] : gr) : -1;
    }
    __syncthreads();

    // load A tile (64 x 256)
    {
        int r = tid >> 2, q4 = tid & 3;
        int tok = stok[r];
        const float* src = item + (size_t)max(tok, 0) * DM;
#pragma unroll
        for (int i = 0; i < 16; ++i) {
            int qd = q4 + i * 4;
            float4 v = make_float4(0.f, 0.f, 0.f, 0.f);
            if (tok >= 0) v = reinterpret_cast<const float4*>(src)[qd];
            *reinterpret_cast<float4*>(&xs[r * XPAD + qd * 4]) = v;
        }
    }
    __syncthreads();

    int wid = tid >> 5, lane = tid & 31;
    int wm = wid >> 2, wn = wid & 3;       // wm: 2 m-pairs; wn: 4 n-slices
    int la = lane >> 2, lb = lane & 3;
    int mbase = wm * 32 + la;
    const float* x0 = &xs[(mbase     ) * XPAD];
    const float* x1 = &xs[(mbase +  8) * XPAD];
    const float* x2 = &xs[(mbase + 16) * XPAD];
    const float* x3 = &xs[(mbase + 24) * XPAD];

    int gr0 = row0 + mbase;
    int tok0 = (gr0      < count) ? (list ? list[gr0]      : gr0)      : -1;
    int tok1 = (gr0 + 8  < count) ? (list ? list[gr0 + 8]  : gr0 + 8)  : -1;
    int tok2 = (gr0 + 16 < count) ? (list ? list[gr0 + 16] : gr0 + 16) : -1;
    int tok3 = (gr0 + 24 < count) ? (list ? list[gr0 + 24] : gr0 + 24) : -1;
    int b0_ = (tok0 >= 0) ? tok0 / LEN : 0, n0_ = (tok0 >= 0) ? tok0 % LEN : 0;
    int b1_ = (tok1 >= 0) ? tok1 / LEN : 0, n1_ = (tok1 >= 0) ? tok1 % LEN : 0;
    int b2_ = (tok2 >= 0) ? tok2 / LEN : 0, n2_ = (tok2 >= 0) ? tok2 % LEN : 0;
    int b3_ = (tok3 >= 0) ? tok3 / LEN : 0, n3_ = (tok3 >= 0) ? tok3 % LEN : 0;

    // ================= pass 0: K columns (full 4xTF32, R13-exact) ==========
    {
        int nsb = wn * 8;
        const uint4* wf = g_WfI + (((size_t)t * 64 + nsb) * 32) * 32 + lane;

        float acc0[8][4], acc1[8][4];
#pragma unroll
        for (int ns = 0; ns < 8; ++ns)
#pragma unroll
            for (int j = 0; j < 4; ++j) { acc0[ns][j] = 0.0f; acc1[ns][j] = 0.0f; }

        for (int ks = 0; ks < 32; ++ks) {
            int k0 = ks * 8;
            float f0 = x0[k0 + lb],     f1 = x1[k0 + lb];
            float f2 = x0[k0 + lb + 4], f3 = x1[k0 + lb + 4];
            unsigned ah0 = f2tf(f0), ah1 = f2tf(f1), ah2 = f2tf(f2), ah3 = f2tf(f3);
            unsigned al0 = f2tf(f0 - __uint_as_float(ah0));
            unsigned al1 = f2tf(f1 - __uint_as_float(ah1));
            unsigned al2 = f2tf(f2 - __uint_as_float(ah2));
            unsigned al3 = f2tf(f3 - __uint_as_float(ah3));
            float g0 = x2[k0 + lb],     g1 = x3[k0 + lb];
            float g2 = x2[k0 + lb + 4], g3 = x3[k0 + lb + 4];
            unsigned ch0 = f2tf(g0), ch1 = f2tf(g1), ch2 = f2tf(g2), ch3 = f2tf(g3);
            unsigned cl0 = f2tf(g0 - __uint_as_float(ch0));
            unsigned cl1 = f2tf(g1 - __uint_as_float(ch1));
            unsigned cl2 = f2tf(g2 - __uint_as_float(ch2));
            unsigned cl3 = f2tf(g3 - __uint_as_float(ch3));
            const uint4* wfk = wf + ks * 32;
#pragma unroll
            for (int ns = 0; ns < 8; ++ns) {
                uint4 w = wfk[(size_t)ns * 1024];
                mma8(acc0[ns], al0, al1, al2, al3, w.z, w.w);   // al*bl
                mma8(acc0[ns], ah0, ah1, ah2, ah3, w.z, w.w);   // ah*bl
                mma8(acc0[ns], al0, al1, al2, al3, w.x, w.y);   // al*bh
                mma8(acc0[ns], ah0, ah1, ah2, ah3, w.x, w.y);   // ah*bh
                mma8(acc1[ns], cl0, cl1, cl2, cl3, w.z, w.w);
                mma8(acc1[ns], ch0, ch1, ch2, ch3, w.z, w.w);
                mma8(acc1[ns], cl0, cl1, cl2, cl3, w.x, w.y);
                mma8(acc1[ns], ch0, ch1, ch2, ch3, w.x, w.y);
            }
        }

#pragma unroll
        for (int ns = 0; ns < 8; ++ns) {
            int cg = (nsb + ns) * 8 + lb * 2;
            int hh = (cg >> 6) & 3, kd = cg & 63;       // cg < 256 -> K matrix
            if (tok0 >= 0)
                *reinterpret_cast<float2*>(&outK[(((size_t)b0_ * NH + hh) * LEN + n0_) * DK + kd]) =
                    make_float2(acc0[ns][0], acc0[ns][1]);
            if (tok1 >= 0)
                *reinterpret_cast<float2*>(&outK[(((size_t)b1_ * NH + hh) * LEN + n1_) * DK + kd]) =
                    make_float2(acc0[ns][2], acc0[ns][3]);
            if (tok2 >= 0)
                *reinterpret_cast<float2*>(&outK[(((size_t)b2_ * NH + hh) * LEN + n2_) * DK + kd]) =
                    make_float2(acc1[ns][0], acc1[ns][1]);
            if (tok3 >= 0)
                *reinterpret_cast<float2*>(&outK[(((size_t)b3_ * NH + hh) * LEN + n3_) * DK + kd]) =
                    make_float2(acc1[ns][2], acc1[ns][3]);
        }
        __syncthreads();
    }

    // ================= pass 1: V columns (3xTF32, al*bl dropped) ===========
    {
        int nsb = (4 + wn) * 8;
        const uint4* wf = g_WfI + (((size_t)t * 64 + nsb) * 32) * 32 + lane;

        float acc0[8][4], acc1[8][4];
#pragma unroll
        for (int ns = 0; ns < 8; ++ns)
#pragma unroll
            for (int j = 0; j < 4; ++j) { acc0[ns][j] = 0.0f; acc1[ns][j] = 0.0f; }

        for (int ks = 0; ks < 32; ++ks) {
            int k0 = ks * 8;
            float f0 = x0[k0 + lb],     f1 = x1[k0 + lb];
            float f2 = x0[k0 + lb + 4], f3 = x1[k0 + lb + 4];
            unsigned ah0 = f2tf(f0), ah1 = f2tf(f1), ah2 = f2tf(f2), ah3 = f2tf(f3);
            unsigned al0 = f2tf(f0 - __uint_as_float(ah0));
            unsigned al1 = f2tf(f1 - __uint_as_float(ah1));
            unsigned al2 = f2tf(f2 - __uint_as_float(ah2));
            unsigned al3 = f2tf(f3 - __uint_as_float(ah3));
            float g0 = x2[k0 + lb],     g1 = x3[k0 + lb];
            float g2 = x2[k0 + lb + 4], g3 = x3[k0 + lb + 4];
            unsigned ch0 = f2tf(g0), ch1 = f2tf(g1), ch2 = f2tf(g2), ch3 = f2tf(g3);
            unsigned cl0 = f2tf(g0 - __uint_as_float(ch0));
            unsigned cl1 = f2tf(g1 - __uint_as_float(ch1));
            unsigned cl2 = f2tf(g2 - __uint_as_float(ch2));
            unsigned cl3 = f2tf(g3 - __uint_as_float(ch3));
            const uint4* wfk = wf + ks * 32;
#pragma unroll
            for (int ns = 0; ns < 8; ++ns) {
                uint4 w = wfk[(size_t)ns * 1024];
                mma8(acc0[ns], ah0, ah1, ah2, ah3, w.z, w.w);   // ah*bl
                mma8(acc0[ns], al0, al1, al2, al3, w.x, w.y);   // al*bh
                mma8(acc0[ns], ah0, ah1, ah2, ah3, w.x, w.y);   // ah*bh
                mma8(acc1[ns], ch0, ch1, ch2, ch3, w.z, w.w);
                mma8(acc1[ns], cl0, cl1, cl2, cl3, w.x, w.y);
                mma8(acc1[ns], ch0, ch1, ch2, ch3, w.x, w.y);
            }
        }

#pragma unroll
        for (int ns = 0; ns < 8; ++ns) {
            int cg = (nsb + ns) * 8 + lb * 2;
            int hh = (cg >> 6) & 3, kd = cg & 63;       // cg >= 256 -> V matrix
            if (tok0 >= 0)
                *reinterpret_cast<float2*>(&outV[(((size_t)b0_ * NH + hh) * LEN + n0_) * DK + kd]) =
                    make_float2(acc0[ns][0], acc0[ns][1]);
            if (tok1 >= 0)
                *reinterpret_cast<float2*>(&outV[(((size_t)b1_ * NH + hh) * LEN + n1_) * DK + kd]) =
                    make_float2(acc0[ns][2], acc0[ns][3]);
            if (tok2 >= 0)
                *reinterpret_cast<float2*>(&outV[(((size_t)b2_ * NH + hh) * LEN + n2_) * DK + kd]) =
                    make_float2(acc1[ns][0], acc1[ns][1]);
            if (tok3 >= 0)
                *reinterpret_cast<float2*>(&outV[(((size_t)b3_ * NH + hh) * LEN + n3_) * DK + kd]) =
                    make_float2(acc1[ns][2], acc1[ns][3]);
        }
    }
}

// ---------------------------------------------------------------------------
// Intent projection GEMM (R13-exact): C[64 x 256], 4xTF32, sequential groups.
// ---------------------------------------------------------------------------
__global__ __launch_bounds__(256, 2)
void proj_q_mma(const float* __restrict__ intent)
{
    int t = blockIdx.y;
    int count = min(g_cntQ[t], CAPQ);
    const int* list = g_listQ + t * CAPQ;
    int row0 = blockIdx.x * MT;
    if (row0 >= count) return;

    extern __shared__ float xs[];              // [MT][XPAD]
    __shared__ int stok[MT];
    int tid = threadIdx.x;

    if (tid < MT) {
        int gr = row0 + tid;
        stok[tid] = (gr < count) ? list[gr] : -1;
    }
    __syncthreads();

    {
        int r = tid >> 2, q4 = tid & 3;
        int tok = stok[r];
        const float* src = intent + (size_t)((tok >= 0 ? tok : 0) % NIS) * DM;
#pragma unroll
        for (int i = 0; i < 16; ++i) {
            int qd = q4 + i * 4;
            float4 v = make_float4(0.f, 0.f, 0.f, 0.f);
            if (tok >= 0) v = reinterpret_cast<const float4*>(src)[qd];
            *reinterpret_cast<float4*>(&xs[r * XPAD + qd * 4]) = v;
        }
    }
    __syncthreads();

    int wid = tid >> 5, lane = tid & 31;
    int wm = wid >> 2, wn = wid & 3;
    int la = lane >> 2, lb = lane & 3;
    int mbase = wm * 32 + la;
    const float* x0 = &xs[(mbase     ) * XPAD];
    const float* x1 = &xs[(mbase +  8) * XPAD];
    const float* x2 = &xs[(mbase + 16) * XPAD];
    const float* x3 = &xs[(mbase + 24) * XPAD];

    int gr0 = row0 + mbase;
    int tok0 = (gr0      < count) ? list[gr0]      : -1;
    int tok1 = (gr0 + 8  < count) ? list[gr0 + 8]  : -1;
    int tok2 = (gr0 + 16 < count) ? list[gr0 + 16] : -1;
    int tok3 = (gr0 + 24 < count) ? list[gr0 + 24] : -1;
    int b0_ = (tok0 >= 0) ? tok0 / NIS : 0, q0_ = (tok0 >= 0) ? tok0 % NIS : 0;
    int b1_ = (tok1 >= 0) ? tok1 / NIS : 0, q1_ = (tok1 >= 0) ? tok1 % NIS : 0;
    int b2_ = (tok2 >= 0) ? tok2 / NIS : 0, q2_ = (tok2 >= 0) ? tok2 % NIS : 0;
    int b3_ = (tok3 >= 0) ? tok3 / NIS : 0, q3_ = (tok3 >= 0) ? tok3 % NIS : 0;

    int nsb = wn * 8;
    const uint4* wf = g_WfQ + (((size_t)t * 32 + nsb) * 32) * 32 + lane;

    float acc0[8][4], acc1[8][4];
#pragma unroll
    for (int ns = 0; ns < 8; ++ns)
#pragma unroll
        for (int j = 0; j < 4; ++j) { acc0[ns][j] = 0.0f; acc1[ns][j] = 0.0f; }

    for (int ks = 0; ks < 32; ++ks) {
        int k0 = ks * 8;
        float f0 = x0[k0 + lb],     f1 = x1[k0 + lb];
        float f2 = x0[k0 + lb + 4], f3 = x1[k0 + lb + 4];
        unsigned ah0 = f2tf(f0), ah1 = f2tf(f1), ah2 = f2tf(f2), ah3 = f2tf(f3);
        unsigned al0 = f2tf(f0 - __uint_as_float(ah0));
        unsigned al1 = f2tf(f1 - __uint_as_float(ah1));
        unsigned al2 = f2tf(f2 - __uint_as_float(ah2));
        unsigned al3 = f2tf(f3 - __uint_as_float(ah3));
        float g0 = x2[k0 + lb],     g1 = x3[k0 + lb];
        float g2 = x2[k0 + lb + 4], g3 = x3[k0 + lb + 4];
        unsigned ch0 = f2tf(g0), ch1 = f2tf(g1), ch2 = f2tf(g2), ch3 = f2tf(g3);
        unsigned cl0 = f2tf(g0 - __uint_as_float(ch0));
        unsigned cl1 = f2tf(g1 - __uint_as_float(ch1));
        unsigned cl2 = f2tf(g2 - __uint_as_float(ch2));
        unsigned cl3 = f2tf(g3 - __uint_as_float(ch3));
        const uint4* wfk = wf + ks * 32;
#pragma unroll
        for (int ns = 0; ns < 8; ++ns) {
            uint4 w = wfk[(size_t)ns * 1024];
            mma8(acc0[ns], al0, al1, al2, al3, w.z, w.w);
            mma8(acc0[ns], ah0, ah1, ah2, ah3, w.z, w.w);
            mma8(acc0[ns], al0, al1, al2, al3, w.x, w.y);
            mma8(acc0[ns], ah0, ah1, ah2, ah3, w.x, w.y);
            mma8(acc1[ns], cl0, cl1, cl2, cl3, w.z, w.w);
            mma8(acc1[ns], ch0, ch1, ch2, ch3, w.z, w.w);
            mma8(acc1[ns], cl0, cl1, cl2, cl3, w.x, w.y);
            mma8(acc1[ns], ch0, ch1, ch2, ch3, w.x, w.y);
        }
    }

#pragma unroll
    for (int ns = 0; ns < 8; ++ns) {
        int cg = (nsb + ns) * 8 + lb * 2;
        int hh = cg >> 6, kd = cg & 63;
        if (tok0 >= 0)
            *reinterpret_cast<float2*>(&g_Q[(((size_t)b0_ * NH + hh) * NIS + q0_) * DK + kd]) =
                make_float2(acc0[ns][0], acc0[ns][1]);
        if (tok1 >= 0)
            *reinterpret_cast<float2*>(&g_Q[(((size_t)b1_ * NH + hh) * NIS + q1_) * DK + kd]) =
                make_float2(acc0[ns][2], acc0[ns][3]);
        if (tok2 >= 0)
            *reinterpret_cast<float2*>(&g_Q[(((size_t)b2_ * NH + hh) * NIS + q2_) * DK + kd]) =
                make_float2(acc1[ns][0], acc1[ns][1]);
        if (tok3 >= 0)
            *reinterpret_cast<float2*>(&g_Q[(((size_t)b3_ * NH + hh) * NIS + q3_) * DK + kd]) =
                make_float2(acc1[ns][2], acc1[ns][3]);
    }
}

// ---------------------------------------------------------------------------
// Attention (R7-exact): scores + softmax + top-k + sparse p@V, int-mask loads.
// ---------------------------------------------------------------------------
__device__ __forceinline__ void mask_scale(float (&p)[25], const int* __restrict__ mrow)
{
#pragma unroll
    for (int i = 0; i < 25; ++i) {
        float s = p[i] * 0.125f;
        if (mrow[i] == 0) s = -1e30f;
        p[i] = s;
    }
}

__device__ __forceinline__ void softmax_topk(float (&p)[25], int g, int nb, int kk,
                                             int qg, float* keptP, int* keptI)
{
    float mx = -3.4e38f;
#pragma unroll
    for (int i = 0; i < 25; ++i) mx = fmaxf(mx, p[i]);
#pragma unroll
    for (int off = 1; off < 8; off <<= 1)
        mx = fmaxf(mx, __shfl_xor_sync(0xffffffffu, mx, off));
    float sum = 0.0f;
#pragma unroll
    for (int i = 0; i < 25; ++i) { float e = expf(p[i] - mx); p[i] = e; sum += e; }
#pragma unroll
    for (int off = 1; off < 8; off <<= 1)
        sum += __shfl_xor_sync(0xffffffffu, sum, off);
    float inv = 1.0f / sum;
#pragma unroll
    for (int i = 0; i < 25; ++i) p[i] *= inv;

    for (int it = 0; it < kk; ++it) {
        float bv = -2.0f; int bi = 0x40000000;
#pragma unroll
        for (int i = 0; i < 25; ++i) {
            if (p[i] > bv) { bv = p[i]; bi = nb + i; }
        }
#pragma unroll
        for (int off = 1; off < 8; off <<= 1) {
            float ov = __shfl_xor_sync(0xffffffffu, bv, off);
            int   oi = __shfl_xor_sync(0xffffffffu, bi, off);
            if (ov > bv || (ov == bv && oi < bi)) { bv = ov; bi = oi; }
        }
#pragma unroll
        for (int i = 0; i < 25; ++i)
            if (nb + i == bi) p[i] = -1.0f;
        if (g == 0) { keptP[qg * 12 + it] = bv; keptI[qg * 12 + it] = bi; }
    }
}

__global__ __launch_bounds__(256, 2)
void attn_kernel(const int* __restrict__ mask,
                 const int* __restrict__ type_cnt,
                 float* __restrict__ out)
{
    extern __shared__ float sm[];
    float* KV    = sm;
    float* Qs    = KV + 64 * LEN;
    float* keptP = Qs + 64 * 65;
    int*   keptI = (int*)(keptP + NIS * 12);
    __shared__ int skk[9];

    int bh = blockIdx.x;
    int b = bh >> 2, h = bh & 3;
    int tid = threadIdx.x;
    int g = tid & 7, qpair = tid >> 3;
    int nb = g * 25;

    if (tid < 9) {
        int v;
        if (tid < 8) v = type_cnt[b * 9 + 1 + tid];
        else { v = 0; for (int i = 0; i < 9; ++i) v += type_cnt[b * 9 + i]; }
        skk[tid] = (int)get_cn((float)v);
    }

    const size_t bhoff = ((size_t)(b * NH + h)) * LEN * DK;
    const size_t qoff  = ((size_t)(b * NH + h)) * NIS * DK;

    {
        const float* Ksrc = g_Kbs + bhoff;
        for (int idx = tid; idx < LEN * DK; idx += 256) {
            int n = idx >> 6, k = idx & 63;
            KV[k * LEN + n] = Ksrc[idx];
        }
    }
    __syncthreads();

    for (int pass = 0; pass < 4; ++pass) {
        int qb = pass * 64;
        for (int idx = tid; idx < 64 * DK; idx += 256) {
            int q = idx >> 6, k = idx & 63;
            Qs[q * 65 + k] = g_Q[qoff + (size_t)(qb + q) * DK + k];
        }
        __syncthreads();

        float p0[25], p1[25];
#pragma unroll
        for (int i = 0; i < 25; ++i) { p0[i] = 0.0f; p1[i] = 0.0f; }
        const float* qrow0 = &Qs[qpair * 65];
        const float* qrow1 = &Qs[(qpair + 32) * 65];
        for (int k = 0; k < DK; ++k) {
            float qv0 = qrow0[k], qv1 = qrow1[k];
            const float* kr = &KV[k * LEN + nb];
#pragma unroll
            for (int i = 0; i < 25; ++i) {
                float kv = kr[i];
                p0[i] = fmaf(qv0, kv, p0[i]);
                p1[i] = fmaf(qv1, kv, p1[i]);
            }
        }
        int q0 = qb + qpair, q1 = q0 + 32;
        mask_scale(p0, mask + ((size_t)b * NIS + q0) * LEN + nb);
        mask_scale(p1, mask + ((size_t)b * NIS + q1) * LEN + nb);
        softmax_topk(p0, g, nb, skk[q0 >> 5], q0, keptP, keptI);
        softmax_topk(p1, g, nb, skk[q1 >> 5], q1, keptP, keptI);
        __syncthreads();
    }

    // ---- Ba scores ----
    {
        const float* Ksrc = g_Kba + bhoff;
        for (int idx = tid; idx < LEN * DK; idx += 256) {
            int n = idx >> 6, k = idx & 63;
            KV[k * LEN + n] = Ksrc[idx];
        }
        for (int idx = tid; idx < 32 * DK; idx += 256) {
            int q = idx >> 6, k = idx & 63;
            Qs[q * 65 + k] = g_Q[qoff + (size_t)(256 + q) * DK + k];
        }
    }
    __syncthreads();
    {
        float p0[25];
#pragma unroll
        for (int i = 0; i < 25; ++i) p0[i] = 0.0f;
        const float* qrow0 = &Qs[qpair * 65];
        for (int k = 0; k < DK; ++k) {
            float qv0 = qrow0[k];
            const float* kr = &KV[k * LEN + nb];
#pragma unroll
            for (int i = 0; i < 25; ++i) p0[i] = fmaf(qv0, kr[i], p0[i]);
        }
        int q0 = 256 + qpair;
        mask_scale(p0, mask + ((size_t)b * NIS + q0) * LEN + nb);
        softmax_topk(p0, g, nb, skk[8], q0, keptP, keptI);
    }
    __syncthreads();

    // ---- Bs sparse output ----
    {
        const float* Vsrc = g_Vbs + bhoff;
        for (int idx = tid; idx < LEN * DK; idx += 256) KV[idx] = Vsrc[idx];
    }
    __syncthreads();
    int qloc = tid >> 3, d0 = (tid & 7) * 8;
    for (int pass = 0; pass < 8; ++pass) {
        int q = pass * 32 + qloc;
        int kk = skk[q >> 5];
        float4 o0 = {0, 0, 0, 0}, o1 = {0, 0, 0, 0};
        for (int j = 0; j < kk; ++j) {
            float pv = keptP[q * 12 + j];
            int   n  = keptI[q * 12 + j];
            const float4* vr = reinterpret_cast<const float4*>(&KV[n * DK + d0]);
            float4 v0 = vr[0], v1 = vr[1];
            o0.x = fmaf(pv, v0.x, o0.x); o0.y = fmaf(pv, v0.y, o0.y);
            o0.z = fmaf(pv, v0.z, o0.z); o0.w = fmaf(pv, v0.w, o0.w);
            o1.x = fmaf(pv, v1.x, o1.x); o1.y = fmaf(pv, v1.y, o1.y);
            o1.z = fmaf(pv, v1.z, o1.z); o1.w = fmaf(pv, v1.w, o1.w);
        }
        float* orow = out + ((size_t)b * NIS + q) * (NH * DK) + h * DK + d0;
        reinterpret_cast<float4*>(orow)[0] = o0;
        reinterpret_cast<float4*>(orow)[1] = o1;
    }
    __syncthreads();

    // ---- Ba sparse output ----
    {
        const float* Vsrc = g_Vba + bhoff;
        for (int idx = tid; idx < LEN * DK; idx += 256) KV[idx] = Vsrc[idx];
    }
    __syncthreads();
    {
        int q = 256 + qloc;
        int kk = skk[8];
        float4 o0 = {0, 0, 0, 0}, o1 = {0, 0, 0, 0};
        for (int j = 0; j < kk; ++j) {
            float pv = keptP[q * 12 + j];
            int   n  = keptI[q * 12 + j];
            const float4* vr = reinterpret_cast<const float4*>(&KV[n * DK + d0]);
            float4 v0 = vr[0], v1 = vr[1];
            o0.x = fmaf(pv, v0.x, o0.x); o0.y = fmaf(pv, v0.y, o0.y);
            o0.z = fmaf(pv, v0.z, o0.z); o0.w = fmaf(pv, v0.w, o0.w);
            o1.x = fmaf(pv, v1.x, o1.x); o1.y = fmaf(pv, v1.y, o1.y);
            o1.z = fmaf(pv, v1.z, o1.z); o1.w = fmaf(pv, v1.w, o1.w);
        }
        float* orow = out + ((size_t)b * NIS + q) * (NH * DK) + h * DK + d0;
        reinterpret_cast<float4*>(orow)[0] = o0;
        reinterpret_cast<float4*>(orow)[1] = o1;
    }
}

// ---------------------------------------------------------------------------
static const int ATTN_SMEM = (64 * LEN + 64 * 65 + NIS * 12) * 4 + NIS * 12 * 4;
static const int PROJ_SMEM = MT * XPAD * 4;   // 66560 B

extern "C" void kernel_launch(void* const* d_in, const int* in_sizes, int n_in,
                              void* d_out, int out_size)
{
    const float* item     = (const float*)d_in[0];
    const float* intent   = (const float*)d_in[1];
    const int*   mask     = (const int*)  d_in[2];
    const int*   b_seq    = (const int*)  d_in[3];
    const int*   b_seq2   = (const int*)  d_in[4];
    const int*   type_cnt = (const int*)  d_in[5];
    const float* W_item   = (const float*)d_in[6];
    const float* W_intent = (const float*)d_in[7];
    float* out = (float*)d_out;

    cudaFuncSetAttribute(attn_kernel,    cudaFuncAttributeMaxDynamicSharedMemorySize, ATTN_SMEM);
    cudaFuncSetAttribute(proj_item_mma,  cudaFuncAttributeMaxDynamicSharedMemorySize, PROJ_SMEM);
    cudaFuncSetAttribute(proj_q_mma,     cudaFuncAttributeMaxDynamicSharedMemorySize, PROJ_SMEM);

    // Launch order keeps proj_item_mma (Bs) in the profiler capture slot (#4).
    zero_cnt_kernel  <<<1, 32>>>();                                          // 1
    build_lists_kernel<<<(NTOK_Q + 255) / 256, 256>>>(b_seq, b_seq2);        // 2
    wfrag_item_kernel<<<(NTI * 64 * 32 * 32 + 255) / 256, 256>>>(W_item);    // 3
    proj_item_mma    <<<dim3(CAPI / MT, NTI), 256, PROJ_SMEM>>>(item, 1);    // 4 <- captured
    wfrag_q_kernel   <<<(NTQ * 32 * 32 * 32 + 255) / 256, 256>>>(W_intent);  // 5
    proj_item_mma    <<<dim3(NTOK_I / MT, 1), 256, PROJ_SMEM>>>(item, 0);    // 6
    proj_q_mma       <<<dim3(CAPQ / MT, NTQ), 256, PROJ_SMEM>>>(intent);     // 7
    attn_kernel      <<<NBATCH * NH, 256, ATTN_SMEM>>>(mask, type_cnt, out); // 8
}